// round 9
// baseline (speedup 1.0000x reference)
#include <cuda_runtime.h>
#include <math.h>

#define NB 64
#define NP 8732
#define NO 32
#define NC 81
#define IMGSZ 224.0f
#define THRESH 0.5f

#define FUSE_THREADS 512
#define HIT ((NP + FUSE_THREADS - 1) / FUSE_THREADS)       // 18
#define ROWS_PER_BLOCK 16
#define CE_BLOCKS ((NB * NP + ROWS_PER_BLOCK - 1) / ROWS_PER_BLOCK)

#define SEL_THREADS 1024
#define SEL_IT ((NP + SEL_THREADS - 1) / SEL_THREADS)       // 9
#define CAP 1024

// ---------------- scratch (all written fresh each run; no reset needed) ----
static __device__ float          g_lse[NB * NP];
static __device__ unsigned char  g_label[NB * NP];
static __device__ int            g_npos[NB];
static __device__ float          g_locsum[NB];
static __device__ float          g_contrib[NB];
static __device__ int            g_done;      // zero-init; last block resets

// ---------------- helpers --------------------------------------------------
__device__ __forceinline__ float warp_sum_f(float v) {
#pragma unroll
    for (int s = 16; s; s >>= 1) v += __shfl_xor_sync(0xffffffffu, v, s);
    return v;
}
__device__ __forceinline__ int warp_sum_i(int v) {
#pragma unroll
    for (int s = 16; s; s >>= 1) v += __shfl_xor_sync(0xffffffffu, v, s);
    return v;
}
__device__ __forceinline__ float warp_max_f(float v) {
#pragma unroll
    for (int s = 16; s; s >>= 1) v = fmaxf(v, __shfl_xor_sync(0xffffffffu, v, s));
    return v;
}

// ======================= K1: fused match+assemble | CE ====================
__global__ void __launch_bounds__(FUSE_THREADS, 2)
k_fused(const float* __restrict__ gt_boxes, const int* __restrict__ gt_labels,
        const float* __restrict__ priors, const float* __restrict__ pred_locs,
        const float* __restrict__ scores) {
    // shared (allocated for all blocks; CE blocks ignore it)
    __shared__ float s_ov[NP];
    __shared__ unsigned char s_obj[NP];
    __shared__ float bx0[NO], by0[NO], bx1[NO], by1[NO], barea[NO];
    __shared__ unsigned long long skey[NO];
    __shared__ int slab[NO], sforced[NO];
    __shared__ float s_red[16];
    __shared__ int   s_redi[16];

    const int tid = threadIdx.x, lane = tid & 31, wid = tid >> 5;

    if (blockIdx.x >= NB) {
        // ---------------- CE path: lse only (label-independent) ------------
        int row = (blockIdx.x - NB) * ROWS_PER_BLOCK + wid;
        if (row >= NB * NP) return;
        const float* r = scores + (size_t)row * NC;
        float x0 = r[lane];
        float x1 = r[lane + 32];
        bool v2 = (lane + 64) < NC;
        float x2 = v2 ? r[lane + 64] : -3.4e38f;
        float m = fmaxf(x0, fmaxf(x1, x2));
        m = warp_max_f(m);
        float e = __expf(x0 - m) + __expf(x1 - m) + (v2 ? __expf(x2 - m) : 0.0f);
        e = warp_sum_f(e);
        if (lane == 0) g_lse[row] = m + __logf(e);
        return;
    }

    // ---------------- heavy path: one block = one image --------------------
    const int b = blockIdx.x;
    if (tid < NO) {
        int o = tid;
        const float* g = gt_boxes + (b * NO + o) * 4;
        float g0 = g[0], g1 = g[1], g2 = g[2], g3 = g[3];
        float x0 = g0 / IMGSZ, y0 = g1 / IMGSZ;
        float x1 = (g0 + g2) / IMGSZ, y1 = (g1 + g3) / IMGSZ;
        bx0[o] = x0; by0[o] = y0; bx1[o] = x1; by1[o] = y1;
        barea[o] = (x1 - x0) * (y1 - y0);
        skey[o] = 0ull;
    }
    __syncthreads();

#pragma unroll 1
    for (int it = 0; it < HIT; it++) {
        const int pw = it * FUSE_THREADS + (wid << 5);   // warp's base prior
        if (pw >= NP) break;                             // no barriers in loop
        const int p = pw + lane;
        const bool valid = p < NP;
        const int pc = valid ? p : NP - 1;
        float4 pr = ((const float4*)priors)[pc];
        float px0 = pr.x - pr.z * 0.5f, py0 = pr.y - pr.w * 0.5f;
        float px1 = pr.x + pr.z * 0.5f, py1 = pr.y + pr.w * 0.5f;
        float parea = (px1 - px0) * (py1 - py0);
        float bv = -1.0f; int bo = 0;
#pragma unroll
        for (int o = 0; o < NO; o++) {
            float lx = fmaxf(bx0[o], px0), ly = fmaxf(by0[o], py0);
            float rx = fminf(bx1[o], px1), ry = fminf(by1[o], py1);
            float w = fmaxf(rx - lx, 0.0f), h = fmaxf(ry - ly, 0.0f);
            float inter = w * h;
            float iou = __fdividef(inter, barea[o] + parea - inter);
            if (!valid) iou = -1.0f;
            if (iou > bv) { bv = iou; bo = o; }
            // per-object best: warp-max, tie -> lowest lane = smallest p
            float m = warp_max_f(iou);
            unsigned mk = __ballot_sync(0xffffffffu, iou == m);
            int leader = __ffs(mk) - 1;
            if (lane == 0) {
                unsigned long long k =
                    ((unsigned long long)__float_as_uint(m) << 32) |
                    (unsigned long long)(0xffffffffu - (unsigned)(pw + leader));
                if (k > skey[o]) atomicMax(&skey[o], k);
            }
        }
        if (valid) { s_ov[p] = bv; s_obj[p] = (unsigned char)bo; }
    }
    __syncthreads();

    if (tid < NO) {
        int o = tid;
        float cx = (bx0[o] + bx1[o]) * 0.5f, cy = (by0[o] + by1[o]) * 0.5f;
        float w = bx1[o] - bx0[o], h = by1[o] - by0[o];
        bx0[o] = cx; by0[o] = cy; bx1[o] = w; by1[o] = h;   // repurpose
        slab[o] = gt_labels[b * NO + o];
        sforced[o] = (int)(0xffffffffu - (unsigned)(skey[o] & 0xffffffffull));
    }
    __syncthreads();

    float locacc = 0.0f;
    int npacc = 0;
    for (int p = tid; p < NP; p += FUSE_THREADS) {
        float ov = s_ov[p];
        int obj = s_obj[p];
#pragma unroll
        for (int o = 0; o < NO; o++)
            if (sforced[o] == p) { obj = o; ov = 1.0f; }   // last o wins
        int lbl = (ov < THRESH) ? 0 : slab[obj];
        g_label[b * NP + p] = (unsigned char)lbl;
        if (lbl != 0) {
            npacc++;
            float4 pr = ((const float4*)priors)[p];
            float tcx = 10.0f * __fdividef(bx0[obj] - pr.x, pr.z);
            float tcy = 10.0f * __fdividef(by0[obj] - pr.y, pr.w);
            float tw = __logf(__fdividef(bx1[obj], pr.z)) * 5.0f;
            float th = __logf(__fdividef(by1[obj], pr.w)) * 5.0f;
            float4 pl = ((const float4*)pred_locs)[b * NP + p];
            float d, s = 0.0f;
            d = fabsf(pl.x - tcx); s += (d < 1.0f) ? 0.5f * d * d : d - 0.5f;
            d = fabsf(pl.y - tcy); s += (d < 1.0f) ? 0.5f * d * d : d - 0.5f;
            d = fabsf(pl.z - tw);  s += (d < 1.0f) ? 0.5f * d * d : d - 0.5f;
            d = fabsf(pl.w - th);  s += (d < 1.0f) ? 0.5f * d * d : d - 0.5f;
            locacc += s;
        }
    }
    locacc = warp_sum_f(locacc);
    npacc = warp_sum_i(npacc);
    if (lane == 0) { s_red[wid] = locacc; s_redi[wid] = npacc; }
    __syncthreads();
    if (tid == 0) {
        float l = 0.0f; int n = 0;
        for (int k = 0; k < 16; k++) { l += s_red[k]; n += s_redi[k]; }
        g_locsum[b] = l;
        g_npos[b] = n;
    }
}

// ======================= K2: top-K select + final =========================
__global__ void __launch_bounds__(SEL_THREADS, 1)
k_sel(const float* __restrict__ scores, float* __restrict__ out) {
    __shared__ float sce[NP];                // negative ce (clamped >= 0)
    __shared__ int   cnt[2048];
    __shared__ float buf[CAP];
    __shared__ float s_f[32];
    __shared__ int   s_sel, s_kcur, s_nc, s_last;
    __shared__ float s_pos, s_gt;

    const int b = blockIdx.x, tid = threadIdx.x, lane = tid & 31, wid = tid >> 5;

    // ---- materialize ce = lse - score[lbl]; split pos / neg ----
    float posacc = 0.0f;
    for (int p = tid; p < NP; p += SEL_THREADS) {
        int lbl = g_label[b * NP + p];
        float ce = g_lse[b * NP + p] -
                   scores[((size_t)b * NP + p) * NC + lbl];
        float c;
        if (lbl) { posacc += ce; c = 0.0f; }
        else       c = fmaxf(ce, 0.0f);
        sce[p] = c;
    }
    posacc = warp_sum_f(posacc);
    if (lane == 0) s_f[wid] = posacc;
    for (int i = tid; i < 2048; i += SEL_THREADS) cnt[i] = 0;
    __syncthreads();

    const int np = g_npos[b];
    int K = 3 * max(np, 1);
    if (K > NP) K = NP;

    // ---- pass 0: 11-bit digit u>>21, histogram with warp aggregation ----
    for (int it = 0; it < SEL_IT; it++) {
        int p = it * SEL_THREADS + tid;
        int key = (p < NP) ? (int)(__float_as_uint(sce[p]) >> 21) : 4096;
        unsigned mm = __match_any_sync(0xffffffffu, key);
        if (lane == __ffs(mm) - 1 && key < 2048) atomicAdd(&cnt[key], __popc(mm));
    }
    __syncthreads();
    if (wid == 0) {        // suffix scan, 64 bins per lane, descending
        int base = 2047 - lane * 64;
        int psum = 0;
        for (int i = 0; i < 64; i++) psum += cnt[base - i];
        int incl = psum;
#pragma unroll
        for (int s = 1; s < 32; s <<= 1) {
            int o = __shfl_up_sync(0xffffffffu, incl, s);
            if (lane >= s) incl += o;
        }
        int excl = incl - psum;
        if (K > excl && K <= excl + psum) {
            int cum = excl;
            for (int i = 0; i < 64; i++) {
                int h = cnt[base - i];
                if (cum + h >= K) { s_sel = base - i; s_kcur = K - cum; break; }
                cum += h;
            }
        }
    }
    if (tid == 0) {
        float pp = 0.0f;
        for (int k = 0; k < 32; k++) pp += s_f[k];
        s_pos = pp; s_nc = 0; s_gt = 0.0f;
    }
    __syncthreads();
    const int sel0 = s_sel;
    int Kcur = s_kcur;

    // ---- sum of strictly-greater bins + compact equal-bin candidates ----
    float gtl = 0.0f;
    for (int it = 0; it < SEL_IT; it++) {
        int p = it * SEL_THREADS + tid;
        float v = (p < NP) ? sce[p] : 0.0f;
        int d = (p < NP) ? (int)(__float_as_uint(v) >> 21) : -1;
        if (d > sel0) gtl += v;
        bool eq = (d == sel0);
        unsigned mm = __ballot_sync(0xffffffffu, eq);
        if (mm) {
            int leader = __ffs(mm) - 1;
            int basepos = 0;
            if (lane == leader) basepos = atomicAdd(&s_nc, __popc(mm));
            basepos = __shfl_sync(0xffffffffu, basepos, leader);
            if (eq) {
                int pos = basepos + __popc(mm & ((1u << lane) - 1u));
                if (pos < CAP) buf[pos] = v;
            }
        }
    }
    gtl = warp_sum_f(gtl);
    if (lane == 0) s_f[wid] = gtl;
    __syncthreads();
    if (tid == 0) {
        float t = 0.0f;
        for (int k = 0; k < 32; k++) t += s_f[k];
        s_gt += t;
    }
    __syncthreads();
    const int Ncand = s_nc;

    unsigned tbits;
    if (Ncand <= CAP) {
        // ---- candidates in registers; passes 1 (11b) and 2 (10b) ----
        bool active = tid < Ncand;
        float v = active ? buf[tid] : 0.0f;
        unsigned u = __float_as_uint(v);
        int sel1 = 0, sel2 = 0;
#pragma unroll
        for (int pass = 1; pass <= 2; pass++) {
            const int nb = (pass == 1) ? 2048 : 1024;
            const int d = (pass == 1) ? (int)((u >> 10) & 0x7FF)
                                      : (int)(u & 0x3FF);
            for (int i = tid; i < nb; i += SEL_THREADS) cnt[i] = 0;
            __syncthreads();
            int key = active ? d : 4096;
            unsigned mm = __match_any_sync(0xffffffffu, key);
            if (lane == __ffs(mm) - 1 && key < nb) atomicAdd(&cnt[key], __popc(mm));
            __syncthreads();
            if (wid == 0) {
                const int per = nb / 32;
                int base = nb - 1 - lane * per;
                int psum = 0;
                for (int i = 0; i < per; i++) psum += cnt[base - i];
                int incl = psum;
#pragma unroll
                for (int s = 1; s < 32; s <<= 1) {
                    int o = __shfl_up_sync(0xffffffffu, incl, s);
                    if (lane >= s) incl += o;
                }
                int excl = incl - psum;
                if (Kcur > excl && Kcur <= excl + psum) {
                    int cum = excl;
                    for (int i = 0; i < per; i++) {
                        int h = cnt[base - i];
                        if (cum + h >= Kcur) { s_sel = base - i; s_kcur = Kcur - cum; break; }
                        cum += h;
                    }
                }
            }
            __syncthreads();
            int sel = s_sel; Kcur = s_kcur;
            float g = (active && d > sel) ? v : 0.0f;
            g = warp_sum_f(g);
            if (lane == 0) s_f[wid] = g;
            __syncthreads();
            if (tid == 0) {
                float t = 0.0f;
                for (int k = 0; k < 32; k++) t += s_f[k];
                s_gt += t;
            }
            active = active && (d == sel);
            if (pass == 1) sel1 = sel; else sel2 = sel;
            __syncthreads();
        }
        tbits = ((unsigned)sel0 << 21) | ((unsigned)sel1 << 10) | (unsigned)sel2;
    } else {
        // ---- fallback: full-scan masked passes (pathological data only) ---
        unsigned pfx = ((unsigned)sel0) << 21;
        unsigned pmask = 0xFFE00000u;
        int sel1 = 0, sel2 = 0;
#pragma unroll
        for (int pass = 1; pass <= 2; pass++) {
            const int nb = (pass == 1) ? 2048 : 1024;
            for (int i = tid; i < nb; i += SEL_THREADS) cnt[i] = 0;
            __syncthreads();
            for (int it = 0; it < SEL_IT; it++) {
                int p = it * SEL_THREADS + tid;
                int key = 4096;
                if (p < NP) {
                    unsigned uu = __float_as_uint(sce[p]);
                    if ((uu & pmask) == pfx)
                        key = (pass == 1) ? (int)((uu >> 10) & 0x7FF)
                                          : (int)(uu & 0x3FF);
                }
                unsigned mm = __match_any_sync(0xffffffffu, key);
                if (lane == __ffs(mm) - 1 && key < nb) atomicAdd(&cnt[key], __popc(mm));
            }
            __syncthreads();
            if (wid == 0) {
                const int per = nb / 32;
                int base = nb - 1 - lane * per;
                int psum = 0;
                for (int i = 0; i < per; i++) psum += cnt[base - i];
                int incl = psum;
#pragma unroll
                for (int s = 1; s < 32; s <<= 1) {
                    int o = __shfl_up_sync(0xffffffffu, incl, s);
                    if (lane >= s) incl += o;
                }
                int excl = incl - psum;
                if (Kcur > excl && Kcur <= excl + psum) {
                    int cum = excl;
                    for (int i = 0; i < per; i++) {
                        int h = cnt[base - i];
                        if (cum + h >= Kcur) { s_sel = base - i; s_kcur = Kcur - cum; break; }
                        cum += h;
                    }
                }
            }
            __syncthreads();
            int sel = s_sel; Kcur = s_kcur;
            float gl = 0.0f;
            for (int it = 0; it < SEL_IT; it++) {
                int p = it * SEL_THREADS + tid;
                if (p < NP) {
                    unsigned uu = __float_as_uint(sce[p]);
                    int dd = (pass == 1) ? (int)((uu >> 10) & 0x7FF)
                                         : (int)(uu & 0x3FF);
                    if ((uu & pmask) == pfx && dd > sel) gl += sce[p];
                }
            }
            gl = warp_sum_f(gl);
            if (lane == 0) s_f[wid] = gl;
            __syncthreads();
            if (tid == 0) {
                float t = 0.0f;
                for (int k = 0; k < 32; k++) t += s_f[k];
                s_gt += t;
            }
            __syncthreads();
            if (pass == 1) {
                sel1 = sel;
                pfx |= (unsigned)sel1 << 10;
                pmask = 0xFFFFFC00u;
            } else sel2 = sel;
        }
        tbits = pfx | (unsigned)sel2;
    }

    // ---- per-image contribution + last-block final reduction ----
    if (tid == 0) {
        float t = __uint_as_float(tbits);
        g_contrib[b] = s_pos + s_gt + (float)Kcur * t;
        __threadfence();
        int old = atomicAdd(&g_done, 1);
        s_last = (old == NB - 1);
    }
    __syncthreads();
    if (s_last) {
        if (tid < NB) {
            volatile float* vc = g_contrib;
            float c = vc[tid];
            int np2 = g_npos[tid];
            float ncl = (float)max(np2, 1);
            float l = g_locsum[tid];
            c = warp_sum_f(c); ncl = warp_sum_f(ncl); l = warp_sum_f(l);
            int tp = warp_sum_i(np2);
            if (lane == 0) {
                int w = tid >> 5;
                s_f[w * 4 + 0] = c; s_f[w * 4 + 1] = ncl; s_f[w * 4 + 2] = l;
                s_f[w * 4 + 3] = (float)tp;
            }
        }
        __syncthreads();
        if (tid == 0) {
            float sumc = s_f[0] + s_f[4];
            float sumnpcl = s_f[1] + s_f[5];
            float suml = s_f[2] + s_f[6];
            long long tp = (long long)s_f[3] + (long long)s_f[7];
            float conf = sumc / sumnpcl;
            long long den = tp * 4; if (den < 1) den = 1;
            float loc = (tp > 0) ? (suml / (float)den) : 0.0f;
            out[0] = conf + loc;
            g_done = 0;                  // reset for next graph replay
        }
    }
}

// ---------------- launch ---------------------------------------------------
extern "C" void kernel_launch(void* const* d_in, const int* in_sizes, int n_in,
                              void* d_out, int out_size) {
    const float* pred_locs   = (const float*)d_in[0];
    const float* pred_scores = (const float*)d_in[1];
    const float* gt_boxes    = (const float*)d_in[2];
    const int*   gt_labels   = (const int*)d_in[3];
    const float* priors      = (const float*)d_in[4];
    float* out = (float*)d_out;

    k_fused<<<NB + CE_BLOCKS, FUSE_THREADS>>>(gt_boxes, gt_labels, priors,
                                              pred_locs, pred_scores);
    k_sel<<<NB, SEL_THREADS>>>(pred_scores, out);
}

// round 14
// speedup vs baseline: 1.8769x; 1.8769x over previous
#include <cuda_runtime.h>
#include <math.h>

#define NB 64
#define NP 8732
#define NO 32
#define NC 81
#define IMGSZ 224.0f
#define THRESH 0.5f

// ---------------- scratch (device globals) ---------------------------------
static __device__ unsigned long long g_objkey[NB * NO];   // packed (iou_bits<<32)|~p
static __device__ float          g_bestov[NB * NP];
static __device__ unsigned char  g_bestobj[NB * NP];
static __device__ unsigned char  g_label[NB * NP];
static __device__ float          g_ce[NB * NP];
static __device__ int            g_npos[NB];
static __device__ float          g_locsum[NB];
static __device__ float          g_contrib[NB];
static __device__ int            g_done;      // zero-init; last block resets

// ---------------- helpers --------------------------------------------------
__device__ __forceinline__ float warp_sum_f(float v) {
#pragma unroll
    for (int s = 16; s; s >>= 1) v += __shfl_xor_sync(0xffffffffu, v, s);
    return v;
}
__device__ __forceinline__ int warp_sum_i(int v) {
#pragma unroll
    for (int s = 16; s; s >>= 1) v += __shfl_xor_sync(0xffffffffu, v, s);
    return v;
}
__device__ __forceinline__ float warp_max_f(float v) {
#pragma unroll
    for (int s = 16; s; s >>= 1) v = fmaxf(v, __shfl_xor_sync(0xffffffffu, v, s));
    return v;
}
__device__ __forceinline__ unsigned long long warp_max_ull(unsigned long long v) {
#pragma unroll
    for (int s = 16; s; s >>= 1) {
        unsigned long long o = __shfl_xor_sync(0xffffffffu, v, s);
        v = (o > v) ? o : v;
    }
    return v;
}

// ---------------- K1: fused matching (per-prior AND per-object best) -------
#define MATCH_BLKS 9
#define MATCH_THREADS 256
#define MATCH_STRIDE (MATCH_BLKS * MATCH_THREADS)   // 2304
#define MATCH_ITERS ((NP + MATCH_STRIDE - 1) / MATCH_STRIDE)  // 4
__global__ void k_match(const float* __restrict__ gt_boxes,
                        const float* __restrict__ priors) {
    const int b = blockIdx.y;
    __shared__ float bx0[NO], by0[NO], bx1[NO], by1[NO], barea[NO];
    __shared__ unsigned long long skey[NO];
    if (threadIdx.x < NO) {
        int o = threadIdx.x;
        const float* g = gt_boxes + (b * NO + o) * 4;
        float g0 = g[0], g1 = g[1], g2 = g[2], g3 = g[3];
        float x0 = g0 / IMGSZ, y0 = g1 / IMGSZ;
        float x1 = (g0 + g2) / IMGSZ, y1 = (g1 + g3) / IMGSZ;
        bx0[o] = x0; by0[o] = y0; bx1[o] = x1; by1[o] = y1;
        barea[o] = (x1 - x0) * (y1 - y0);
        skey[o] = 0ull;
    }
    __syncthreads();

    const int lane = threadIdx.x & 31;
#pragma unroll
    for (int it = 0; it < MATCH_ITERS; it++) {
        int p = blockIdx.x * MATCH_THREADS + threadIdx.x + it * MATCH_STRIDE;
        bool valid = p < NP;
        int pc = valid ? p : NP - 1;
        float4 pr = ((const float4*)priors)[pc];
        float px0 = pr.x - pr.z * 0.5f, py0 = pr.y - pr.w * 0.5f;
        float px1 = pr.x + pr.z * 0.5f, py1 = pr.y + pr.w * 0.5f;
        float parea = (px1 - px0) * (py1 - py0);
        float bv = -1.0f; int bo = 0;
        const unsigned long long lowbits =
            (unsigned long long)(0xffffffffu - (unsigned)pc);
#pragma unroll
        for (int o = 0; o < NO; o++) {
            float lx = fmaxf(bx0[o], px0), ly = fmaxf(by0[o], py0);
            float rx = fminf(bx1[o], px1), ry = fminf(by1[o], py1);
            float w = fmaxf(rx - lx, 0.0f), h = fmaxf(ry - ly, 0.0f);
            float inter = w * h;
            float iou = __fdividef(inter, barea[o] + parea - inter);
            if (iou > bv) { bv = iou; bo = o; }
            unsigned long long k = valid
                ? (((unsigned long long)__float_as_uint(iou) << 32) | lowbits)
                : 0ull;
            bool want = k > skey[o];
            unsigned m = __ballot_sync(0xffffffffu, want);
            if (m) {
                unsigned long long kk = want ? k : 0ull;
                kk = warp_max_ull(kk);
                if (lane == 0) atomicMax(&skey[o], kk);
            }
        }
        if (valid) {
            g_bestov[b * NP + p] = bv;
            g_bestobj[b * NP + p] = (unsigned char)bo;
        }
    }
    __syncthreads();
    if (threadIdx.x < NO)
        atomicMax(&g_objkey[b * NO + threadIdx.x], skey[threadIdx.x]);
}

// ---------------- K2: labels + true_locs + SmoothL1 partials ---------------
__global__ void k_assemble(const float* __restrict__ gt_boxes,
                           const int* __restrict__ gt_labels,
                           const float* __restrict__ priors,
                           const float* __restrict__ pred_locs) {
    const int b = blockIdx.y;
    __shared__ float scx[NO], scy[NO], sww[NO], shh[NO];
    __shared__ int slab[NO], sforced[NO];
    __shared__ float s_loc[8];
    __shared__ int s_np[8];

    if (threadIdx.x < NO) {
        int o = threadIdx.x;
        const float* g = gt_boxes + (b * NO + o) * 4;
        float g0 = g[0], g1 = g[1], g2 = g[2], g3 = g[3];
        float x0 = g0 / IMGSZ, y0 = g1 / IMGSZ;
        float x1 = (g0 + g2) / IMGSZ, y1 = (g1 + g3) / IMGSZ;
        scx[o] = (x0 + x1) * 0.5f; scy[o] = (y0 + y1) * 0.5f;
        sww[o] = x1 - x0;          shh[o] = y1 - y0;
        slab[o] = gt_labels[b * NO + o];
        sforced[o] = (int)(0xffffffffu - (unsigned)(g_objkey[b * NO + o] & 0xffffffffull));
    }
    __syncthreads();

    float locacc = 0.0f;
    int npacc = 0;
    const int stride = gridDim.x * blockDim.x;
    for (int p = blockIdx.x * blockDim.x + threadIdx.x; p < NP; p += stride) {
        float ov = g_bestov[b * NP + p];
        int obj = g_bestobj[b * NP + p];
#pragma unroll
        for (int o = 0; o < NO; o++)
            if (sforced[o] == p) { obj = o; ov = 1.0f; }  // last o wins
        int lbl = (ov < THRESH) ? 0 : slab[obj];
        g_label[b * NP + p] = (unsigned char)lbl;
        if (lbl != 0) {
            npacc++;
            float4 pr = ((const float4*)priors)[p];
            float tcx = 10.0f * __fdividef(scx[obj] - pr.x, pr.z);
            float tcy = 10.0f * __fdividef(scy[obj] - pr.y, pr.w);
            float tw = __logf(__fdividef(sww[obj], pr.z)) * 5.0f;
            float th = __logf(__fdividef(shh[obj], pr.w)) * 5.0f;
            float4 pl = ((const float4*)pred_locs)[b * NP + p];
            float d, s = 0.0f;
            d = fabsf(pl.x - tcx); s += (d < 1.0f) ? 0.5f * d * d : d - 0.5f;
            d = fabsf(pl.y - tcy); s += (d < 1.0f) ? 0.5f * d * d : d - 0.5f;
            d = fabsf(pl.z - tw);  s += (d < 1.0f) ? 0.5f * d * d : d - 0.5f;
            d = fabsf(pl.w - th);  s += (d < 1.0f) ? 0.5f * d * d : d - 0.5f;
            locacc += s;
        }
    }
    locacc = warp_sum_f(locacc);
    npacc = warp_sum_i(npacc);
    int lane = threadIdx.x & 31, wid = threadIdx.x >> 5;
    if (lane == 0) { s_loc[wid] = locacc; s_np[wid] = npacc; }
    __syncthreads();
    if (threadIdx.x == 0) {
        float l = 0.0f; int n = 0;
        for (int k = 0; k < 8; k++) { l += s_loc[k]; n += s_np[k]; }
        atomicAdd(&g_locsum[b], l);
        atomicAdd(&g_npos[b], n);
    }
}

// ---------------- K3: per-(b,p) cross entropy (warp per row, full ce) ------
__global__ void k_ce(const float* __restrict__ scores) {
    const int gw = (blockIdx.x * blockDim.x + threadIdx.x) >> 5;
    const int lane = threadIdx.x & 31;
    if (gw >= NB * NP) return;
    const float* row = scores + (size_t)gw * NC;
    float x0 = row[lane];
    float x1 = row[lane + 32];
    bool v2 = (lane + 64) < NC;
    float x2 = v2 ? row[lane + 64] : -3.4e38f;
    float m = fmaxf(x0, fmaxf(x1, x2));
    m = warp_max_f(m);
    float e = __expf(x0 - m) + __expf(x1 - m) + (v2 ? __expf(x2 - m) : 0.0f);
    e = warp_sum_f(e);
    if (lane == 0) {
        int lbl = g_label[gw];
        g_ce[gw] = m + __logf(e) - row[lbl];
    }
}

// ---------------- K4: top-K (register-candidate radix) + fused final -------
#define TK_THREADS 1024
#define TK_IT ((NP + TK_THREADS - 1) / TK_THREADS)   // 9
#define CAP 1024
__global__ void __launch_bounds__(TK_THREADS, 1)
k_topk(float* __restrict__ out) {
    __shared__ float sce[NP];
    __shared__ int   cnt[2048];
    __shared__ float buf[CAP];
    __shared__ float s_f[32];
    __shared__ int   s_sel, s_kcur, s_nc, s_last;
    __shared__ float s_pos, s_gt;

    const int b = blockIdx.x, tid = threadIdx.x, lane = tid & 31, wid = tid >> 5;

    float posacc = 0.0f;
    for (int p = tid; p < NP; p += TK_THREADS) {
        float c = g_ce[b * NP + p];
        if (g_label[b * NP + p]) { posacc += c; c = 0.0f; }
        else                      c = fmaxf(c, 0.0f);
        sce[p] = c;
    }
    posacc = warp_sum_f(posacc);
    if (lane == 0) s_f[wid] = posacc;
    for (int i = tid; i < 2048; i += TK_THREADS) cnt[i] = 0;
    __syncthreads();

    const int np = g_npos[b];
    int K = 3 * max(np, 1);
    if (K > NP) K = NP;

    // ---- pass 0: 11-bit digit u>>21 (ce>=0 so u>>21 <= 1019 < 2048) ----
    for (int it = 0; it < TK_IT; it++) {
        int p = it * TK_THREADS + tid;
        int key = (p < NP) ? (int)(__float_as_uint(sce[p]) >> 21) : 4096;
        unsigned mm = __match_any_sync(0xffffffffu, key);
        if (lane == __ffs(mm) - 1 && key < 2048) atomicAdd(&cnt[key], __popc(mm));
    }
    __syncthreads();
    if (wid == 0) {        // suffix scan, 64 bins/lane descending
        int base = 2047 - lane * 64;
        int psum = 0;
        for (int i = 0; i < 64; i++) psum += cnt[base - i];
        int incl = psum;
#pragma unroll
        for (int s = 1; s < 32; s <<= 1) {
            int o = __shfl_up_sync(0xffffffffu, incl, s);
            if (lane >= s) incl += o;
        }
        int excl = incl - psum;
        if (K > excl && K <= excl + psum) {
            int cum = excl;
            for (int i = 0; i < 64; i++) {
                int h = cnt[base - i];
                if (cum + h >= K) { s_sel = base - i; s_kcur = K - cum; break; }
                cum += h;
            }
        }
    }
    if (tid == 0) {
        float pp = 0.0f;
        for (int k = 0; k < 32; k++) pp += s_f[k];
        s_pos = pp; s_nc = 0; s_gt = 0.0f;
    }
    __syncthreads();
    const int sel0 = s_sel;
    int Kcur = s_kcur;

    // ---- sum strictly-greater bins + compact equal-bin candidates ----
    float gtl = 0.0f;
    for (int it = 0; it < TK_IT; it++) {
        int p = it * TK_THREADS + tid;
        float v = (p < NP) ? sce[p] : 0.0f;
        int d = (p < NP) ? (int)(__float_as_uint(v) >> 21) : -1;
        if (d > sel0) gtl += v;
        bool eq = (d == sel0);
        unsigned mm = __ballot_sync(0xffffffffu, eq);
        if (mm) {
            int leader = __ffs(mm) - 1;
            int basepos = 0;
            if (lane == leader) basepos = atomicAdd(&s_nc, __popc(mm));
            basepos = __shfl_sync(0xffffffffu, basepos, leader);
            if (eq) {
                int pos = basepos + __popc(mm & ((1u << lane) - 1u));
                if (pos < CAP) buf[pos] = v;
            }
        }
    }
    gtl = warp_sum_f(gtl);
    if (lane == 0) s_f[wid] = gtl;
    __syncthreads();
    if (tid == 0) {
        float t = 0.0f;
        for (int k = 0; k < 32; k++) t += s_f[k];
        s_gt += t;
    }
    __syncthreads();
    const int Ncand = s_nc;

    unsigned tbits;
    if (Ncand <= CAP) {
        bool active = tid < Ncand;
        float v = active ? buf[tid] : 0.0f;
        unsigned u = __float_as_uint(v);
        int sel1 = 0, sel2 = 0;
#pragma unroll
        for (int pass = 1; pass <= 2; pass++) {
            const int nb = (pass == 1) ? 2048 : 1024;
            const int d = (pass == 1) ? (int)((u >> 10) & 0x7FF)
                                      : (int)(u & 0x3FF);
            for (int i = tid; i < nb; i += TK_THREADS) cnt[i] = 0;
            __syncthreads();
            int key = active ? d : 4096;
            unsigned mm = __match_any_sync(0xffffffffu, key);
            if (lane == __ffs(mm) - 1 && key < nb) atomicAdd(&cnt[key], __popc(mm));
            __syncthreads();
            if (wid == 0) {
                const int per = nb / 32;
                int base = nb - 1 - lane * per;
                int psum = 0;
                for (int i = 0; i < per; i++) psum += cnt[base - i];
                int incl = psum;
#pragma unroll
                for (int s = 1; s < 32; s <<= 1) {
                    int o = __shfl_up_sync(0xffffffffu, incl, s);
                    if (lane >= s) incl += o;
                }
                int excl = incl - psum;
                if (Kcur > excl && Kcur <= excl + psum) {
                    int cum = excl;
                    for (int i = 0; i < per; i++) {
                        int h = cnt[base - i];
                        if (cum + h >= Kcur) { s_sel = base - i; s_kcur = Kcur - cum; break; }
                        cum += h;
                    }
                }
            }
            __syncthreads();
            int sel = s_sel; Kcur = s_kcur;
            float g = (active && d > sel) ? v : 0.0f;
            g = warp_sum_f(g);
            if (lane == 0) s_f[wid] = g;
            __syncthreads();
            if (tid == 0) {
                float t = 0.0f;
                for (int k = 0; k < 32; k++) t += s_f[k];
                s_gt += t;
            }
            active = active && (d == sel);
            if (pass == 1) sel1 = sel; else sel2 = sel;
            __syncthreads();
        }
        tbits = ((unsigned)sel0 << 21) | ((unsigned)sel1 << 10) | (unsigned)sel2;
    } else {
        // fallback: full-scan masked passes (pathological tie storms only)
        unsigned pfx = ((unsigned)sel0) << 21;
        unsigned pmask = 0xFFE00000u;
        int sel2 = 0;
#pragma unroll
        for (int pass = 1; pass <= 2; pass++) {
            const int nb = (pass == 1) ? 2048 : 1024;
            for (int i = tid; i < nb; i += TK_THREADS) cnt[i] = 0;
            __syncthreads();
            for (int it = 0; it < TK_IT; it++) {
                int p = it * TK_THREADS + tid;
                int key = 4096;
                if (p < NP) {
                    unsigned uu = __float_as_uint(sce[p]);
                    if ((uu & pmask) == pfx)
                        key = (pass == 1) ? (int)((uu >> 10) & 0x7FF)
                                          : (int)(uu & 0x3FF);
                }
                unsigned mm = __match_any_sync(0xffffffffu, key);
                if (lane == __ffs(mm) - 1 && key < nb) atomicAdd(&cnt[key], __popc(mm));
            }
            __syncthreads();
            if (wid == 0) {
                const int per = nb / 32;
                int base = nb - 1 - lane * per;
                int psum = 0;
                for (int i = 0; i < per; i++) psum += cnt[base - i];
                int incl = psum;
#pragma unroll
                for (int s = 1; s < 32; s <<= 1) {
                    int o = __shfl_up_sync(0xffffffffu, incl, s);
                    if (lane >= s) incl += o;
                }
                int excl = incl - psum;
                if (Kcur > excl && Kcur <= excl + psum) {
                    int cum = excl;
                    for (int i = 0; i < per; i++) {
                        int h = cnt[base - i];
                        if (cum + h >= Kcur) { s_sel = base - i; s_kcur = Kcur - cum; break; }
                        cum += h;
                    }
                }
            }
            __syncthreads();
            int sel = s_sel; Kcur = s_kcur;
            float gl = 0.0f;
            for (int it = 0; it < TK_IT; it++) {
                int p = it * TK_THREADS + tid;
                if (p < NP) {
                    unsigned uu = __float_as_uint(sce[p]);
                    int dd = (pass == 1) ? (int)((uu >> 10) & 0x7FF)
                                         : (int)(uu & 0x3FF);
                    if ((uu & pmask) == pfx && dd > sel) gl += sce[p];
                }
            }
            gl = warp_sum_f(gl);
            if (lane == 0) s_f[wid] = gl;
            __syncthreads();
            if (tid == 0) {
                float t = 0.0f;
                for (int k = 0; k < 32; k++) t += s_f[k];
                s_gt += t;
            }
            __syncthreads();
            if (pass == 1) { pfx |= (unsigned)sel << 10; pmask = 0xFFFFFC00u; }
            else sel2 = sel;
        }
        tbits = pfx | (unsigned)sel2;
    }

    // ---- per-image contribution + last-block final reduction --------------
    // NOTE: non-last blocks must NOT reset any scratch — the last block reads
    // g_npos/g_locsum for ALL images below. All resets happen in the last
    // block, after the final output is written. (This was the R12 race.)
    if (tid == 0) {
        float t = __uint_as_float(tbits);
        g_contrib[b] = s_pos + s_gt + (float)Kcur * t;
        __threadfence();
        int old = atomicAdd(&g_done, 1);
        s_last = (old == NB - 1);
    }
    __syncthreads();
    if (s_last) {
        if (tid < NB) {
            volatile float* vc = g_contrib;
            volatile int*   vn = g_npos;
            volatile float* vl = g_locsum;
            float c = vc[tid];
            int np2 = vn[tid];
            float ncl = (float)max(np2, 1);
            float l = vl[tid];
            c = warp_sum_f(c); ncl = warp_sum_f(ncl); l = warp_sum_f(l);
            int tp = warp_sum_i(np2);
            if (lane == 0) {
                int w = tid >> 5;
                s_f[w * 4 + 0] = c; s_f[w * 4 + 1] = ncl;
                s_f[w * 4 + 2] = l; s_f[w * 4 + 3] = (float)tp;
            }
        }
        __syncthreads();
        if (tid == 0) {
            float sumc = s_f[0] + s_f[4];
            float sumnpcl = s_f[1] + s_f[5];
            float suml = s_f[2] + s_f[6];
            long long tp = (long long)s_f[3] + (long long)s_f[7];
            float conf = sumc / sumnpcl;
            long long den = tp * 4; if (den < 1) den = 1;
            float loc = (tp > 0) ? (suml / (float)den) : 0.0f;
            out[0] = conf + loc;
        }
        __syncthreads();   // all final reads done -> safe to reset scratch
        for (int i = tid; i < NB * NO; i += TK_THREADS) g_objkey[i] = 0ull;
        if (tid < NB) { g_npos[tid] = 0; g_locsum[tid] = 0.0f; }
        if (tid == 0) g_done = 0;      // reset for next graph replay
    }
}

// ---------------- launch ---------------------------------------------------
extern "C" void kernel_launch(void* const* d_in, const int* in_sizes, int n_in,
                              void* d_out, int out_size) {
    const float* pred_locs   = (const float*)d_in[0];
    const float* pred_scores = (const float*)d_in[1];
    const float* gt_boxes    = (const float*)d_in[2];
    const int*   gt_labels   = (const int*)d_in[3];
    const float* priors      = (const float*)d_in[4];
    float* out = (float*)d_out;

    k_match<<<dim3(MATCH_BLKS, NB), MATCH_THREADS>>>(gt_boxes, priors);
    k_assemble<<<dim3(9, NB), 256>>>(gt_boxes, gt_labels, priors, pred_locs);
    k_ce<<<(NB * NP * 32 + 511) / 512, 512>>>(pred_scores);
    k_topk<<<NB, TK_THREADS>>>(out);
}